// round 6
// baseline (speedup 1.0000x reference)
#include <cuda_runtime.h>
#include <cstdint>
#include <cstddef>

#define NN 8192
#define BLOCKS 8          // 8 blocks * 1024 threads = 8192 threads (1:1 neurons)
#define THREADS 1024
#define WARPS (THREADS / 32)

__device__ __forceinline__ uint32_t rotl32(uint32_t x, int r) {
    return (x << r) | (x >> (32 - r));
}

// Threefry-2x32, key = (0, 42): exact replica of JAX's PRNG core.
__device__ __forceinline__ void threefry2x32_key0_42(uint32_t c0, uint32_t c1,
                                                     uint32_t& o0, uint32_t& o1) {
    const uint32_t ks0 = 0u;
    const uint32_t ks1 = 42u;
    const uint32_t ks2 = ks0 ^ ks1 ^ 0x1BD11BDAu;
    uint32_t x0 = c0 + ks0;
    uint32_t x1 = c1 + ks1;
#define TF_ROUND(r) { x0 += x1; x1 = rotl32(x1, (r)); x1 ^= x0; }
    TF_ROUND(13) TF_ROUND(15) TF_ROUND(26) TF_ROUND(6)
    x0 += ks1; x1 += ks2 + 1u;
    TF_ROUND(17) TF_ROUND(29) TF_ROUND(16) TF_ROUND(24)
    x0 += ks2; x1 += ks0 + 2u;
    TF_ROUND(13) TF_ROUND(15) TF_ROUND(26) TF_ROUND(6)
    x0 += ks0; x1 += ks1 + 3u;
    TF_ROUND(17) TF_ROUND(29) TF_ROUND(16) TF_ROUND(24)
    x0 += ks1; x1 += ks2 + 4u;
    TF_ROUND(13) TF_ROUND(15) TF_ROUND(26) TF_ROUND(6)
    x0 += ks2; x1 += ks0 + 5u;
#undef TF_ROUND
    o0 = x0; o1 = x1;
}

// ---------------------------------------------------------------------------
// Single fused kernel. Thread i = neuron i (8 blocks x 1024 threads).
//
// Cross-element dependency (I_syn[i] = sum_j w[i,j]*eps[j], j != i) handled by
// each block redundantly scanning all 8192 (tss, tau_s) pairs with a CHEAP,
// CONSERVATIVE predicate for "eps[j] could be nonzero":
//     eps = (1+tanh(t)) * exp(-t/ts) / ts  is exactly 0 whenever
//     expf(-t/ts) underflows to 0 (arg < ~-103.97). We test arg >= -110
//     (margin for rcp rounding). Predicate may over-fire (-> correct slow
//     path), never under-fires.
// If any element fires, the slow path computes ACCURATE eps into smem and
// runs a warp-per-row matvec for this block's rows (fully correct, unused
// for this dataset).
// ---------------------------------------------------------------------------
__global__ void gif_fused_kernel(const float* __restrict__ I_ext,
                                 const float* __restrict__ w,
                                 const float* __restrict__ v,
                                 const float* __restrict__ spiked,
                                 const float* __restrict__ tss,
                                 const float* __restrict__ theta_v,
                                 const float* __restrict__ tau_m,
                                 const float* __restrict__ tau_s,
                                 const float* __restrict__ tau_theta,
                                 const float* __restrict__ J_theta,
                                 const float* __restrict__ E_L,
                                 const float* __restrict__ c,
                                 const float* __restrict__ Delta_u,
                                 const float* __restrict__ theta_inf,
                                 float* __restrict__ out) {
    const int tid = threadIdx.x;
    const int i   = blockIdx.x * THREADS + tid;

    // ---- per-neuron theta update (accurate math, matches reference) ----
    float th = theta_v[i] + (theta_inf[i] - theta_v[i] + J_theta[i] * spiked[i]) / tau_theta[i];

    // ---- block-local conservative scan: could any eps[j] be nonzero? ----
    const float4* tss4  = reinterpret_cast<const float4*>(tss);
    const float4* taus4 = reinterpret_cast<const float4*>(tau_s);
    bool mine = false;
    #pragma unroll
    for (int k = 0; k < NN / 4 / THREADS; ++k) {          // 2 iterations
        float4 t4 = tss4[tid + k * THREADS];
        float4 s4 = taus4[tid + k * THREADS];
        #pragma unroll
        for (int q = 0; q < 4; ++q) {
            float t   = (&t4.x)[q] - 1.0f;
            float arg = -t * __frcp_rn((&s4.x)[q]);       // -t / tau_s
            mine |= (arg >= -110.0f);                      // exp surely 0 below
        }
    }
    unsigned b = __ballot_sync(0xffffffffu, mine);
    __shared__ unsigned s_w[WARPS];
    if ((tid & 31) == 0) s_w[tid >> 5] = b;
    __syncthreads();
    unsigned any = 0u;
    #pragma unroll
    for (int k = 0; k < WARPS; ++k) any |= s_w[k];

    // ---- I_syn ----
    float Isyn = 0.0f;
    if (any) {
        // Slow path (not taken for this dataset, fully correct):
        // accurate eps into smem, warp-per-row matvec for this block's rows.
        __shared__ float s_eps[NN];                        // 32 KB
        for (int j = tid; j < NN; j += THREADS) {
            float t  = tss[j] - 1.0f;
            float ts = tau_s[j];
            s_eps[j] = (1.0f + tanhf(t)) * expf(-t / ts) / ts;
        }
        __syncthreads();

        __shared__ float s_isyn[THREADS];
        int warp = tid >> 5, lane = tid & 31;
        for (int rr = 0; rr < THREADS / WARPS; ++rr) {     // 32 rows per warp
            int local_row = warp * (THREADS / WARPS) + rr;
            int row = blockIdx.x * THREADS + local_row;
            const float* wr = w + (size_t)row * NN;
            float sum = 0.0f;
            for (int cidx = lane; cidx < NN; cidx += 32)
                sum += wr[cidx] * s_eps[cidx];
            #pragma unroll
            for (int off = 16; off > 0; off >>= 1)
                sum += __shfl_down_sync(0xffffffffu, sum, off);
            if (lane == 0)
                s_isyn[local_row] = sum - wr[row] * s_eps[row];  // mask diagonal
        }
        __syncthreads();
        Isyn = s_isyn[tid];
    }

    // ---- membrane update + spike rate (accurate math) ----
    float vi = v[i];
    float v_next = vi + (E_L[i] - vi + I_ext[i]) / tau_m[i] + Isyn;

    float not_ref = (tss[i] > 2.0f) ? 1.0f : 0.0f;        // T_REFRACTORY = 2
    float lam = not_ref * c[i] * expf((v_next - th) / Delta_u[i]);
    lam = fminf(fmaxf(lam, 0.0f), 1.0f);                  // jnp.clip(..., 0, 1)

    // ---- partitionable threefry Bernoulli: counter (0, i), bits = o0 ^ o1 ----
    uint32_t o0, o1;
    threefry2x32_key0_42(0u, (uint32_t)i, o0, o1);
    uint32_t bits = o0 ^ o1;
    float u = __uint_as_float((bits >> 9) | 0x3F800000u) - 1.0f;  // [0,1)

    float s     = (u < lam) ? 1.0f : 0.0f;
    float v_new = (s != 0.0f) ? 0.0f : v_next;            // RESET_POTENTIAL = 0

    out[i]          = lam;
    out[NN + i]     = s;
    out[2 * NN + i] = v_new;
}

// ---------------------------------------------------------------------------
// Launch. Inputs in setup_inputs order; w located dynamically via its size.
// ---------------------------------------------------------------------------
extern "C" void kernel_launch(void* const* d_in, const int* in_sizes, int n_in,
                              void* d_out, int out_size) {
    const float* vecs[16];
    const float* w = nullptr;
    int nv = 0;
    for (int k = 0; k < n_in; ++k) {
        if (in_sizes[k] == NN * NN) w = (const float*)d_in[k];
        else                        vecs[nv++] = (const float*)d_in[k];
    }
    // Order (w removed): I_ext, v, spiked, time_since_spike, theta_v,
    // tau_m, tau_s, tau_theta, J_theta, E_L, c, Delta_u, theta_inf
    gif_fused_kernel<<<BLOCKS, THREADS>>>(
        vecs[0],  // I_ext
        w,
        vecs[1],  // v
        vecs[2],  // spiked
        vecs[3],  // time_since_spike
        vecs[4],  // theta_v
        vecs[5],  // tau_m
        vecs[6],  // tau_s
        vecs[7],  // tau_theta
        vecs[8],  // J_theta
        vecs[9],  // E_L
        vecs[10], // c
        vecs[11], // Delta_u
        vecs[12], // theta_inf
        (float*)d_out);
}

// round 7
// speedup vs baseline: 1.3092x; 1.3092x over previous
#include <cuda_runtime.h>
#include <cstdint>
#include <cstddef>

#define NN 8192
#define BLOCKS 8          // 8 blocks * 1024 threads = 8192 threads (1:1 neurons)
#define THREADS 1024
#define WARPS (THREADS / 32)

__device__ __forceinline__ uint32_t rotl32(uint32_t x, int r) {
    return (x << r) | (x >> (32 - r));
}

// Threefry-2x32, key = (0, 42): exact replica of JAX's PRNG core.
__device__ __forceinline__ void threefry2x32_key0_42(uint32_t c0, uint32_t c1,
                                                     uint32_t& o0, uint32_t& o1) {
    const uint32_t ks0 = 0u;
    const uint32_t ks1 = 42u;
    const uint32_t ks2 = ks0 ^ ks1 ^ 0x1BD11BDAu;
    uint32_t x0 = c0 + ks0;
    uint32_t x1 = c1 + ks1;
#define TF_ROUND(r) { x0 += x1; x1 = rotl32(x1, (r)); x1 ^= x0; }
    TF_ROUND(13) TF_ROUND(15) TF_ROUND(26) TF_ROUND(6)
    x0 += ks1; x1 += ks2 + 1u;
    TF_ROUND(17) TF_ROUND(29) TF_ROUND(16) TF_ROUND(24)
    x0 += ks2; x1 += ks0 + 2u;
    TF_ROUND(13) TF_ROUND(15) TF_ROUND(26) TF_ROUND(6)
    x0 += ks0; x1 += ks1 + 3u;
    TF_ROUND(17) TF_ROUND(29) TF_ROUND(16) TF_ROUND(24)
    x0 += ks1; x1 += ks2 + 4u;
    TF_ROUND(13) TF_ROUND(15) TF_ROUND(26) TF_ROUND(6)
    x0 += ks2; x1 += ks0 + 5u;
#undef TF_ROUND
    o0 = x0; o1 = x1;
}

// ---------------------------------------------------------------------------
// Single fused kernel. Thread i = neuron i (8 blocks x 1024 threads).
//
// Cross-element dependency (I_syn[i] = sum_j w[i,j]*eps[j], j != i) handled by
// each block redundantly scanning all 8192 (tss, tau_s) pairs with a CHEAP,
// CONSERVATIVE, ALU-only predicate for "eps[j] could be nonzero":
//     eps = (1+tanh(t)) * exp(-t/ts) / ts  is exactly 0 whenever
//     exp(-t/ts) underflows (arg = -t/ts < ~-103.97).
//     arg < -110  <=>  (ts > 0 && t > 110*ts).   Fire otherwise.
// Predicate may over-fire (-> correct slow path), never under-fires.
// If any element fires, the slow path computes ACCURATE eps into smem and
// runs a warp-per-row matvec for this block's rows (fully correct, unused
// for this dataset).
// ---------------------------------------------------------------------------
__global__ void gif_fused_kernel(const float* __restrict__ I_ext,
                                 const float* __restrict__ w,
                                 const float* __restrict__ v,
                                 const float* __restrict__ spiked,
                                 const float* __restrict__ tss,
                                 const float* __restrict__ theta_v,
                                 const float* __restrict__ tau_m,
                                 const float* __restrict__ tau_s,
                                 const float* __restrict__ tau_theta,
                                 const float* __restrict__ J_theta,
                                 const float* __restrict__ E_L,
                                 const float* __restrict__ c,
                                 const float* __restrict__ Delta_u,
                                 const float* __restrict__ theta_inf,
                                 float* __restrict__ out) {
    const int tid = threadIdx.x;
    const int i   = blockIdx.x * THREADS + tid;

    // ---- front-load every per-neuron scattered read (overlap latencies) ----
    float r_thv  = theta_v[i];
    float r_thi  = theta_inf[i];
    float r_Jth  = J_theta[i];
    float r_spk  = spiked[i];
    float r_tth  = tau_theta[i];
    float r_v    = v[i];
    float r_EL   = E_L[i];
    float r_Iext = I_ext[i];
    float r_tm   = tau_m[i];
    float r_tssi = tss[i];
    float r_c    = c[i];
    float r_Du   = Delta_u[i];

    // ---- block-local conservative scan: could any eps[j] be nonzero? ----
    const float4* tss4  = reinterpret_cast<const float4*>(tss);
    const float4* taus4 = reinterpret_cast<const float4*>(tau_s);
    bool mine = false;
    #pragma unroll
    for (int k = 0; k < NN / 4 / THREADS; ++k) {          // 2 iterations
        float4 t4 = tss4[tid + k * THREADS];
        float4 s4 = taus4[tid + k * THREADS];
        #pragma unroll
        for (int q = 0; q < 4; ++q) {
            float t  = (&t4.x)[q] - 1.0f;
            float ts = (&s4.x)[q];
            // safe-zero region: ts > 0 and t > 110*ts  ->  exp underflows
            mine |= !((ts > 0.0f) && (t > 110.0f * ts));
        }
    }
    unsigned b = __ballot_sync(0xffffffffu, mine);
    __shared__ unsigned s_w[WARPS];
    if ((tid & 31) == 0) s_w[tid >> 5] = b;
    __syncthreads();
    unsigned any = 0u;
    #pragma unroll
    for (int k = 0; k < WARPS; ++k) any |= s_w[k];

    // ---- I_syn ----
    float Isyn = 0.0f;
    if (any) {
        // Slow path (not taken for this dataset, fully correct):
        // accurate eps into smem, warp-per-row matvec for this block's rows.
        __shared__ float s_eps[NN];                        // 32 KB
        for (int j = tid; j < NN; j += THREADS) {
            float t  = tss[j] - 1.0f;
            float ts = tau_s[j];
            s_eps[j] = (1.0f + tanhf(t)) * expf(-t / ts) / ts;
        }
        __syncthreads();

        __shared__ float s_isyn[THREADS];
        int warp = tid >> 5, lane = tid & 31;
        for (int rr = 0; rr < THREADS / WARPS; ++rr) {     // 32 rows per warp
            int local_row = warp * (THREADS / WARPS) + rr;
            int row = blockIdx.x * THREADS + local_row;
            const float* wr = w + (size_t)row * NN;
            float sum = 0.0f;
            for (int cidx = lane; cidx < NN; cidx += 32)
                sum += wr[cidx] * s_eps[cidx];
            #pragma unroll
            for (int off = 16; off > 0; off >>= 1)
                sum += __shfl_down_sync(0xffffffffu, sum, off);
            if (lane == 0)
                s_isyn[local_row] = sum - wr[row] * s_eps[row];  // mask diagonal
        }
        __syncthreads();
        Isyn = s_isyn[tid];
    }

    // ---- per-neuron theta update (accurate math, matches reference) ----
    float th = r_thv + (r_thi - r_thv + r_Jth * r_spk) / r_tth;

    // ---- membrane update + spike rate (accurate math) ----
    float v_next = r_v + (r_EL - r_v + r_Iext) / r_tm + Isyn;

    float not_ref = (r_tssi > 2.0f) ? 1.0f : 0.0f;        // T_REFRACTORY = 2
    float lam = not_ref * r_c * expf((v_next - th) / r_Du);
    lam = fminf(fmaxf(lam, 0.0f), 1.0f);                  // jnp.clip(..., 0, 1)

    // ---- partitionable threefry Bernoulli: counter (0, i), bits = o0 ^ o1 ----
    uint32_t o0, o1;
    threefry2x32_key0_42(0u, (uint32_t)i, o0, o1);
    uint32_t bits = o0 ^ o1;
    float u = __uint_as_float((bits >> 9) | 0x3F800000u) - 1.0f;  // [0,1)

    float s     = (u < lam) ? 1.0f : 0.0f;
    float v_new = (s != 0.0f) ? 0.0f : v_next;            // RESET_POTENTIAL = 0

    out[i]          = lam;
    out[NN + i]     = s;
    out[2 * NN + i] = v_new;
}

// ---------------------------------------------------------------------------
// Launch. Inputs in setup_inputs order; w located dynamically via its size.
// ---------------------------------------------------------------------------
extern "C" void kernel_launch(void* const* d_in, const int* in_sizes, int n_in,
                              void* d_out, int out_size) {
    const float* vecs[16];
    const float* w = nullptr;
    int nv = 0;
    for (int k = 0; k < n_in; ++k) {
        if (in_sizes[k] == NN * NN) w = (const float*)d_in[k];
        else                        vecs[nv++] = (const float*)d_in[k];
    }
    // Order (w removed): I_ext, v, spiked, time_since_spike, theta_v,
    // tau_m, tau_s, tau_theta, J_theta, E_L, c, Delta_u, theta_inf
    gif_fused_kernel<<<BLOCKS, THREADS>>>(
        vecs[0],  // I_ext
        w,
        vecs[1],  // v
        vecs[2],  // spiked
        vecs[3],  // time_since_spike
        vecs[4],  // theta_v
        vecs[5],  // tau_m
        vecs[6],  // tau_s
        vecs[7],  // tau_theta
        vecs[8],  // J_theta
        vecs[9],  // E_L
        vecs[10], // c
        vecs[11], // Delta_u
        vecs[12], // theta_inf
        (float*)d_out);
}